// round 2
// baseline (speedup 1.0000x reference)
#include <cuda_runtime.h>

#define NN 200000
#define EE 600000
#define GG 8192
#define HH 128

// Scratch (allocation-free rule: __device__ globals)
__device__ float g_dinv[NN];
__device__ float g_h[(long long)NN * HH];     // h = X @ W (pre-aggregation)
__device__ float g_agg[(long long)NN * HH];   // aggregation accumulator
__device__ float g_cnt[GG];

// ---------------- degree / dinv ----------------
__global__ void k_init_deg() {
    int i = blockIdx.x * blockDim.x + threadIdx.x;
    if (i < NN) g_dinv[i] = 1.0f;   // self-loop contributes 1
}

__global__ void k_accum_deg(const int* __restrict__ dst) {
    int e = blockIdx.x * blockDim.x + threadIdx.x;
    if (e < EE) atomicAdd(&g_dinv[__ldg(&dst[e])], 1.0f);
}

__global__ void k_finish_dinv() {
    int i = blockIdx.x * blockDim.x + threadIdx.x;
    if (i < NN) g_dinv[i] = rsqrtf(g_dinv[i]);
}

// ---------------- fused GEMM ----------------
// Computes C = In @ W where:
//   In = A (N x K)                          if A != nullptr   (layer 1, K=30)
//   In = relu(g_agg + bias)  (N x 128)      if A == nullptr   (layers 2/3)
// Writes g_h = C and g_agg = C * dinv^2 (self-loop init for next scatter).
// Block: 256 threads, 128 rows x 128 cols, 8x8 per thread, BK=32.
__global__ __launch_bounds__(256, 2) void k_gemm(
    const float* __restrict__ A, const float* __restrict__ W,
    const float* __restrict__ bias, int K)
{
    __shared__ float As[32][132];   // [k][m]
    __shared__ float Ws[32][132];   // [k][n]
    const int tid = threadIdx.x;
    const int r0  = blockIdx.x * 128;
    const int tx  = tid & 15;       // 16 col-tiles of 8
    const int ty  = tid >> 4;       // 16 row-tiles of 8

    float acc[8][8];
    #pragma unroll
    for (int i = 0; i < 8; i++)
        #pragma unroll
        for (int j = 0; j < 8; j++) acc[i][j] = 0.0f;

    for (int k0 = 0; k0 < K; k0 += 32) {
        // Load A tile 128x32 (coalesced: warp covers 32 consecutive k in a row)
        #pragma unroll
        for (int i = 0; i < 16; i++) {
            int f   = i * 256 + tid;
            int row = f >> 5, kk = f & 31;
            int gr = r0 + row, gk = k0 + kk;
            float v = 0.0f;
            if (gr < NN && gk < K) {
                if (A) v = __ldg(&A[(long long)gr * K + gk]);
                else   v = fmaxf(g_agg[(long long)gr * 128 + gk] + bias[gk], 0.0f);
            }
            As[kk][row] = v;
        }
        // Load W tile 32x128 (fully coalesced)
        #pragma unroll
        for (int i = 0; i < 16; i++) {
            int f  = i * 256 + tid;
            int kk = f >> 7, n = f & 127;
            int gk = k0 + kk;
            Ws[kk][n] = (gk < K) ? __ldg(&W[gk * 128 + n]) : 0.0f;
        }
        __syncthreads();

        #pragma unroll
        for (int kk = 0; kk < 32; kk++) {
            float4 a0 = *(const float4*)&As[kk][ty * 8];
            float4 a1 = *(const float4*)&As[kk][ty * 8 + 4];
            float4 b0 = *(const float4*)&Ws[kk][tx * 8];
            float4 b1 = *(const float4*)&Ws[kk][tx * 8 + 4];
            float a[8] = {a0.x, a0.y, a0.z, a0.w, a1.x, a1.y, a1.z, a1.w};
            float b[8] = {b0.x, b0.y, b0.z, b0.w, b1.x, b1.y, b1.z, b1.w};
            #pragma unroll
            for (int i = 0; i < 8; i++)
                #pragma unroll
                for (int j = 0; j < 8; j++)
                    acc[i][j] += a[i] * b[j];
        }
        __syncthreads();
    }

    // Epilogue: h = acc ; agg = acc * dinv^2  (self-loop term, norm = 1/deg)
    #pragma unroll
    for (int i = 0; i < 8; i++) {
        int gr = r0 + ty * 8 + i;
        if (gr < NN) {
            float dv = g_dinv[gr];
            float d2 = dv * dv;
            long long base = (long long)gr * 128 + tx * 8;
            #pragma unroll
            for (int j = 0; j < 8; j += 4) {
                float4 hv = make_float4(acc[i][j], acc[i][j+1], acc[i][j+2], acc[i][j+3]);
                *(float4*)&g_h[base + j]   = hv;
                float4 av = make_float4(hv.x * d2, hv.y * d2, hv.z * d2, hv.w * d2);
                *(float4*)&g_agg[base + j] = av;
            }
        }
    }
}

// ---------------- edge scatter ----------------
// One warp per edge: agg[dst] += h[src] * (dinv[src]*dinv[dst])
// Each lane handles one float4 (32 lanes x 4 = 128), vector RED (sm_90+).
__global__ __launch_bounds__(256) void k_scatter(const int* __restrict__ src,
                                                 const int* __restrict__ dst)
{
    int w = (blockIdx.x * 256 + threadIdx.x) >> 5;
    if (w >= EE) return;
    int lane = threadIdx.x & 31;
    int s = __ldg(&src[w]), d = __ldg(&dst[w]);
    float c = g_dinv[s] * g_dinv[d];
    float4 v = *((const float4*)g_h + (long long)s * 32 + lane);
    float* p = g_agg + (long long)d * 128 + lane * 4;
    asm volatile("red.global.add.v4.f32 [%0], {%1, %2, %3, %4};"
                 :: "l"(p), "f"(v.x * c), "f"(v.y * c), "f"(v.z * c), "f"(v.w * c)
                 : "memory");
}

// ---------------- pooling ----------------
__global__ void k_zero_out(float* __restrict__ out) {
    int i = blockIdx.x * blockDim.x + threadIdx.x;
    if (i < (GG * HH) / 4) ((float4*)out)[i] = make_float4(0.f, 0.f, 0.f, 0.f);
    if (i < GG) g_cnt[i] = 0.0f;
}

// warp per node: out[batch[n]] += relu(agg[n] + b3) ; cnt[batch[n]] += 1
__global__ __launch_bounds__(256) void k_pool(const int* __restrict__ batch,
                                              const float* __restrict__ b3,
                                              float* __restrict__ out)
{
    int w = (blockIdx.x * 256 + threadIdx.x) >> 5;
    if (w >= NN) return;
    int lane = threadIdx.x & 31;
    int g = __ldg(&batch[w]);
    float4 a  = *((const float4*)g_agg + (long long)w * 32 + lane);
    float4 bb = ((const float4*)b3)[lane];
    float x0 = fmaxf(a.x + bb.x, 0.0f);
    float x1 = fmaxf(a.y + bb.y, 0.0f);
    float x2 = fmaxf(a.z + bb.z, 0.0f);
    float x3 = fmaxf(a.w + bb.w, 0.0f);
    float* p = out + (long long)g * 128 + lane * 4;
    asm volatile("red.global.add.v4.f32 [%0], {%1, %2, %3, %4};"
                 :: "l"(p), "f"(x0), "f"(x1), "f"(x2), "f"(x3) : "memory");
    if (lane == 0) atomicAdd(&g_cnt[g], 1.0f);
}

__global__ void k_div(float* __restrict__ out) {
    int i = blockIdx.x * blockDim.x + threadIdx.x;
    if (i < GG * HH) {
        float c = g_cnt[i >> 7];
        out[i] *= 1.0f / fmaxf(c, 1.0f);
    }
}

// ---------------- launch ----------------
extern "C" void kernel_launch(void* const* d_in, const int* in_sizes, int n_in,
                              void* d_out, int out_size)
{
    const float* x     = (const float*)d_in[0];   // [N, 30]
    const int*   ei    = (const int*)  d_in[1];   // [2, E]
    const int*   batch = (const int*)  d_in[2];   // [N]
    const float* W1    = (const float*)d_in[3];
    const float* b1    = (const float*)d_in[4];
    const float* W2    = (const float*)d_in[5];
    const float* b2    = (const float*)d_in[6];
    const float* W3    = (const float*)d_in[7];
    const float* b3    = (const float*)d_in[8];
    float* out = (float*)d_out;

    const int* src = ei;
    const int* dst = ei + EE;

    k_init_deg   <<<(NN + 255) / 256, 256>>>();
    k_accum_deg  <<<(EE + 255) / 256, 256>>>(dst);
    k_finish_dinv<<<(NN + 255) / 256, 256>>>();

    const int GB = (NN + 127) / 128;          // 1563 gemm blocks
    const int SB = (EE * 32 + 255) / 256;     // 75000 scatter blocks

    // Layer 1: input x (K=30)
    k_gemm   <<<GB, 256>>>(x, W1, nullptr, 30);
    k_scatter<<<SB, 256>>>(src, dst);
    // Layer 2: input relu(agg + b1)
    k_gemm   <<<GB, 256>>>(nullptr, W2, b1, 128);
    k_scatter<<<SB, 256>>>(src, dst);
    // Layer 3: input relu(agg + b2)
    k_gemm   <<<GB, 256>>>(nullptr, W3, b2, 128);
    k_scatter<<<SB, 256>>>(src, dst);

    // Global mean pool of relu(agg + b3)
    k_zero_out<<<(GG * HH / 4 + 255) / 256, 256>>>(out);
    k_pool    <<<(NN * 32 + 255) / 256, 256>>>(batch, b3, out);
    k_div     <<<(GG * HH + 255) / 256, 256>>>(out);
}

// round 4
// speedup vs baseline: 1.6657x; 1.6657x over previous
#include <cuda_runtime.h>

#define NN 200000
#define EE 600000
#define GG 8192
#define HH 128

#define SCT 512
#define SCE 4
#define SCCHUNK (SCT * SCE)                      // 2048
#define SCB ((NN + SCCHUNK - 1) / SCCHUNK)       // 98

// Scratch (allocation-free rule: __device__ globals)
__device__ float g_dinv[NN];
__device__ int   g_cnt_i[NN];
__device__ int   g_rowptr[NN + 1];
__device__ int   g_cursor[NN];
__device__ int   g_col[EE];
__device__ float g_coef[EE];
__device__ int   g_bsum[SCB];
__device__ float g_h[(long long)NN * HH];
__device__ float g_agg[(long long)NN * HH];
__device__ float g_cntf[GG];

// ---------------- degree / counts ----------------
__global__ void k_init() {
    int i = blockIdx.x * blockDim.x + threadIdx.x;
    if (i < NN) g_cnt_i[i] = 0;
}

__global__ void k_count(const int* __restrict__ dst) {
    int e = blockIdx.x * blockDim.x + threadIdx.x;
    if (e < EE) atomicAdd(&g_cnt_i[__ldg(&dst[e])], 1);
}

__global__ void k_dinv() {
    int i = blockIdx.x * blockDim.x + threadIdx.x;
    if (i < NN) g_dinv[i] = rsqrtf(1.0f + (float)g_cnt_i[i]);
}

// ---------------- exclusive scan of g_cnt_i -> g_rowptr ----------------
__global__ void k_scan1() {
    __shared__ int wsum[SCT / 32];
    int t = threadIdx.x, b = blockIdx.x;
    int base = b * SCCHUNK + t * SCE;
    int s = 0;
    #pragma unroll
    for (int i = 0; i < SCE; i++) {
        int idx = base + i;
        if (idx < NN) s += g_cnt_i[idx];
    }
    int lane = t & 31, wid = t >> 5;
    #pragma unroll
    for (int o = 16; o > 0; o >>= 1) s += __shfl_down_sync(0xffffffffu, s, o);
    if (lane == 0) wsum[wid] = s;
    __syncthreads();
    if (wid == 0) {
        int v = (lane < SCT / 32) ? wsum[lane] : 0;
        #pragma unroll
        for (int o = 16; o > 0; o >>= 1) v += __shfl_down_sync(0xffffffffu, v, o);
        if (lane == 0) g_bsum[b] = v;
    }
}

__global__ void k_scan2() {
    if (threadIdx.x == 0) {
        int run = 0;
        for (int b = 0; b < SCB; b++) { int t = g_bsum[b]; g_bsum[b] = run; run += t; }
        g_rowptr[NN] = run;
    }
}

__global__ void k_scan3() {
    __shared__ int wsum[SCT / 32];
    __shared__ int wexcl[SCT / 32];
    int t = threadIdx.x, b = blockIdx.x;
    int base = b * SCCHUNK + t * SCE;
    int p[SCE];
    int run = 0;
    #pragma unroll
    for (int i = 0; i < SCE; i++) {
        int idx = base + i;
        int e = (idx < NN) ? g_cnt_i[idx] : 0;
        p[i] = run; run += e;
    }
    int lane = t & 31, wid = t >> 5;
    int v = run;
    #pragma unroll
    for (int o = 1; o < 32; o <<= 1) {
        int u = __shfl_up_sync(0xffffffffu, v, o);
        if (lane >= o) v += u;
    }
    int texcl = v - run;
    if (lane == 31) wsum[wid] = v;
    __syncthreads();
    if (wid == 0) {
        int w = (lane < SCT / 32) ? wsum[lane] : 0;
        int vv = w;
        #pragma unroll
        for (int o = 1; o < 32; o <<= 1) {
            int u = __shfl_up_sync(0xffffffffu, vv, o);
            if (lane >= o) vv += u;
        }
        if (lane < SCT / 32) wexcl[lane] = vv - w;
    }
    __syncthreads();
    int off = g_bsum[b] + wexcl[wid] + texcl;
    #pragma unroll
    for (int i = 0; i < SCE; i++) {
        int idx = base + i;
        if (idx < NN) { g_rowptr[idx] = off + p[i]; g_cursor[idx] = off + p[i]; }
    }
}

// ---------------- CSR fill ----------------
__global__ void k_fill(const int* __restrict__ src, const int* __restrict__ dst) {
    int e = blockIdx.x * blockDim.x + threadIdx.x;
    if (e >= EE) return;
    int s = __ldg(&src[e]), d = __ldg(&dst[e]);
    int pos = atomicAdd(&g_cursor[d], 1);
    g_col[pos]  = s;
    g_coef[pos] = g_dinv[s] * g_dinv[d];
}

// ---------------- aggregation (gather) ----------------
// 30-dim: warp per node, lanes 0..29. aggX[n] = x[n]*dinv^2 + sum_nbr x[s]*coef
// Output stored with row stride 32 into g_agg.
__global__ __launch_bounds__(256) void k_agg30(const float* __restrict__ x) {
    int n = (blockIdx.x * 256 + threadIdx.x) >> 5;
    if (n >= NN) return;
    int lane = threadIdx.x & 31;
    int beg = __ldg(&g_rowptr[n]), end = __ldg(&g_rowptr[n + 1]);
    float dv = g_dinv[n];
    float acc = 0.0f;
    if (lane < 30) acc = __ldg(&x[(long long)n * 30 + lane]) * dv * dv;
    for (int j = beg; j < end; j++) {
        int s = __ldg(&g_col[j]);
        float c = __ldg(&g_coef[j]);
        if (lane < 30) acc += __ldg(&x[(long long)s * 30 + lane]) * c;
    }
    if (lane < 30) g_agg[(long long)n * 32 + lane] = acc;
}

// 128-dim: warp per node, lane handles one float4.
// g_agg[n] = g_h[n]*dinv^2 + sum_nbr g_h[s]*coef
__global__ __launch_bounds__(256) void k_agg128() {
    int n = (blockIdx.x * 256 + threadIdx.x) >> 5;
    if (n >= NN) return;
    int lane = threadIdx.x & 31;
    int beg = __ldg(&g_rowptr[n]), end = __ldg(&g_rowptr[n + 1]);
    float dv = g_dinv[n];
    const float4* h4 = (const float4*)g_h;
    float4 a = h4[(long long)n * 32 + lane];
    float d2 = dv * dv;
    float4 acc = make_float4(a.x * d2, a.y * d2, a.z * d2, a.w * d2);
    for (int j = beg; j < end; j++) {
        int s = __ldg(&g_col[j]);
        float c = __ldg(&g_coef[j]);
        float4 v = h4[(long long)s * 32 + lane];
        acc.x += v.x * c; acc.y += v.y * c; acc.z += v.z * c; acc.w += v.w * c;
    }
    ((float4*)g_agg)[(long long)n * 32 + lane] = acc;
}

// ---------------- GEMM: g_h = relu(g_agg @ W + bias) ----------------
// Input is ALWAYS the device-global g_agg (never passed from host!).
// K=30 -> lda=32 (k_agg30 layout), K=128 -> lda=128.
// Block: 128 rows x 128 cols, 8x8 per thread, BK=32.
__global__ __launch_bounds__(256, 2) void k_gemm(
    const float* __restrict__ W, const float* __restrict__ bias,
    int K, int lda)
{
    __shared__ float As[32][132];   // [k][m]
    __shared__ float Ws[32][132];   // [k][n]
    const int tid = threadIdx.x;
    const int r0  = blockIdx.x * 128;
    const int tx  = tid & 15;
    const int ty  = tid >> 4;

    float acc[8][8];
    #pragma unroll
    for (int i = 0; i < 8; i++)
        #pragma unroll
        for (int j = 0; j < 8; j++) acc[i][j] = 0.0f;

    for (int k0 = 0; k0 < K; k0 += 32) {
        #pragma unroll
        for (int i = 0; i < 16; i++) {
            int f   = i * 256 + tid;
            int row = f >> 5, kk = f & 31;
            int gr = r0 + row, gk = k0 + kk;
            float v = 0.0f;
            if (gr < NN && gk < K) v = g_agg[(long long)gr * lda + gk];
            As[kk][row] = v;
        }
        #pragma unroll
        for (int i = 0; i < 16; i++) {
            int f  = i * 256 + tid;
            int kk = f >> 7, n = f & 127;
            int gk = k0 + kk;
            Ws[kk][n] = (gk < K) ? __ldg(&W[gk * 128 + n]) : 0.0f;
        }
        __syncthreads();

        #pragma unroll
        for (int kk = 0; kk < 32; kk++) {
            float4 a0 = *(const float4*)&As[kk][ty * 8];
            float4 a1 = *(const float4*)&As[kk][ty * 8 + 4];
            float4 b0 = *(const float4*)&Ws[kk][tx * 8];
            float4 b1 = *(const float4*)&Ws[kk][tx * 8 + 4];
            float a[8] = {a0.x, a0.y, a0.z, a0.w, a1.x, a1.y, a1.z, a1.w};
            float b[8] = {b0.x, b0.y, b0.z, b0.w, b1.x, b1.y, b1.z, b1.w};
            #pragma unroll
            for (int i = 0; i < 8; i++)
                #pragma unroll
                for (int j = 0; j < 8; j++)
                    acc[i][j] += a[i] * b[j];
        }
        __syncthreads();
    }

    float4 bb0 = ((const float4*)bias)[tx * 2];
    float4 bb1 = ((const float4*)bias)[tx * 2 + 1];
    float bv[8] = {bb0.x, bb0.y, bb0.z, bb0.w, bb1.x, bb1.y, bb1.z, bb1.w};

    #pragma unroll
    for (int i = 0; i < 8; i++) {
        int gr = r0 + ty * 8 + i;
        if (gr < NN) {
            long long base = (long long)gr * 128 + tx * 8;
            #pragma unroll
            for (int j = 0; j < 8; j += 4) {
                float4 hv = make_float4(fmaxf(acc[i][j]     + bv[j],     0.0f),
                                        fmaxf(acc[i][j + 1] + bv[j + 1], 0.0f),
                                        fmaxf(acc[i][j + 2] + bv[j + 2], 0.0f),
                                        fmaxf(acc[i][j + 3] + bv[j + 3], 0.0f));
                *(float4*)&g_h[base + j] = hv;
            }
        }
    }
}

// ---------------- pooling ----------------
__global__ void k_zero_out(float* __restrict__ out) {
    int i = blockIdx.x * blockDim.x + threadIdx.x;
    if (i < (GG * HH) / 4) ((float4*)out)[i] = make_float4(0.f, 0.f, 0.f, 0.f);
    if (i < GG) g_cntf[i] = 0.0f;
}

// warp per node: out[batch[n]] += g_h[n] (already relu'd) ; cnt[batch[n]] += 1
__global__ __launch_bounds__(256) void k_pool(const int* __restrict__ batch,
                                              float* __restrict__ out)
{
    int w = (blockIdx.x * 256 + threadIdx.x) >> 5;
    if (w >= NN) return;
    int lane = threadIdx.x & 31;
    int g = __ldg(&batch[w]);
    float4 a = *((const float4*)g_h + (long long)w * 32 + lane);
    float* p = out + (long long)g * 128 + lane * 4;
    asm volatile("red.global.add.v4.f32 [%0], {%1, %2, %3, %4};"
                 :: "l"(p), "f"(a.x), "f"(a.y), "f"(a.z), "f"(a.w) : "memory");
    if (lane == 0) atomicAdd(&g_cntf[g], 1.0f);
}

__global__ void k_div(float* __restrict__ out) {
    int i = blockIdx.x * blockDim.x + threadIdx.x;
    if (i < GG * HH) {
        float c = g_cntf[i >> 7];
        out[i] *= 1.0f / fmaxf(c, 1.0f);
    }
}

// ---------------- launch ----------------
extern "C" void kernel_launch(void* const* d_in, const int* in_sizes, int n_in,
                              void* d_out, int out_size)
{
    const float* x     = (const float*)d_in[0];   // [N, 30]
    const int*   ei    = (const int*)  d_in[1];   // [2, E]
    const int*   batch = (const int*)  d_in[2];   // [N]
    const float* W1    = (const float*)d_in[3];
    const float* b1    = (const float*)d_in[4];
    const float* W2    = (const float*)d_in[5];
    const float* b2    = (const float*)d_in[6];
    const float* W3    = (const float*)d_in[7];
    const float* b3    = (const float*)d_in[8];
    float* out = (float*)d_out;

    const int* src = ei;
    const int* dst = ei + EE;

    // CSR build (by dst) + dinv
    k_init <<<(NN + 255) / 256, 256>>>();
    k_count<<<(EE + 255) / 256, 256>>>(dst);
    k_dinv <<<(NN + 255) / 256, 256>>>();
    k_scan1<<<SCB, SCT>>>();
    k_scan2<<<1, 32>>>();
    k_scan3<<<SCB, SCT>>>();
    k_fill <<<(EE + 255) / 256, 256>>>(src, dst);

    const int GB = (NN + 127) / 128;          // 1563 gemm blocks
    const int AB = (NN * 32 + 255) / 256;     // 25000 warp-per-node blocks

    // Layer 1: agg in input space (30-dim), then h1 = relu(aggX @ W1 + b1)
    k_agg30 <<<AB, 256>>>(x);
    k_gemm  <<<GB, 256>>>(W1, b1, 30, 32);
    // Layer 2
    k_agg128<<<AB, 256>>>();
    k_gemm  <<<GB, 256>>>(W2, b2, 128, 128);
    // Layer 3
    k_agg128<<<AB, 256>>>();
    k_gemm  <<<GB, 256>>>(W3, b3, 128, 128);

    // Global mean pool of g_h
    k_zero_out<<<(GG * HH / 4 + 255) / 256, 256>>>(out);
    k_pool    <<<(NN * 32 + 255) / 256, 256>>>(batch, out);
    k_div     <<<(GG * HH + 255) / 256, 256>>>(out);
}